// round 12
// baseline (speedup 1.0000x reference)
#include <cuda_runtime.h>
#include <math.h>

// Problem dims
#define Bq   32
#define Sq   256
#define Iq   128
#define Hq   512
#define Cq   64
#define BUFD 17
#define OUTL 64

#define NCTA 128      // 2 groups x 64 CTAs
#define GCTA 64       // CTAs per group
#define RB   16       // batches per group
#define NTHR 256
#define SHS  516      // activation row stride (floats)
#define WCOLS 24      // 8 h-cols * 3 outputs
#define WSTRIDE 516   // weight col stride (floats)
#define QOFF (WCOLS * WSTRIDE + 4)   // 12388: Q-variant block offset (bank-shifted)

// ---------------- device globals ----------------
__device__ __align__(16) float g_Pt[Hq * Hq];        // W_pass @ W_tau
__device__ __align__(16) float g_Pm[Hq * Hq];        // W_pass @ W_mem
__device__ __align__(16) float g_bc[Hq];             // b_in @ W_pass + b_pass
__device__ __align__(16) float g_WE[2 * Hq * 3 * Hq];// [(v*512+jg)*3+o][k] col-major weight sets
__device__ __align__(16) float g_MX[2 * Iq * 2048];  // x-side matrices, [v][k][jg*4+o]
__device__ __align__(16) float g_bias4[2 * 2048];    // folded biases, [v][jg*4+o]
__device__ __align__(16) float g_XW[(size_t)Bq * Sq * 2048]; // per-(b,t) precomputed terms (64MB)
__device__ __align__(16) float g_h0[2 * Bq * Hq];    // double-buffered h0 broadcast
__device__ unsigned g_bar[128];                      // 2 group counters, 256B apart

// ---------------- k_pre1: Pt, Pm, bc, zero h0/bar ----------------
__global__ void k_pre1(const float* __restrict__ Wp, const float* __restrict__ Wt,
                       const float* __restrict__ Wm, const float* __restrict__ b_in,
                       const float* __restrict__ b_pass) {
    int blk = blockIdx.x, tid = threadIdx.x;
    if (blk < 512) {
        int id = blk * 256 + tid;          // [0, 131072)
        int mat = id >> 16;                // 0: Pt, 1: Pm
        int m = (id >> 7) & 511;
        int jq = (id & 127) << 2;
        const float* B = mat ? Wm : Wt;
        float4 acc = make_float4(0.f, 0.f, 0.f, 0.f);
#pragma unroll 4
        for (int u = 0; u < Hq; ++u) {
            float a = __ldg(Wp + m * Hq + u);
            float4 w = __ldg((const float4*)(B + u * Hq + jq));
            acc.x = fmaf(a, w.x, acc.x); acc.y = fmaf(a, w.y, acc.y);
            acc.z = fmaf(a, w.z, acc.z); acc.w = fmaf(a, w.w, acc.w);
        }
        *(float4*)((mat ? g_Pm : g_Pt) + m * Hq + jq) = acc;
    } else if (blk < 520) {
        int id = (blk - 512) * 256 + tid;  // [0, 2048): zero both h0 parities
        float4 z = make_float4(0.f, 0.f, 0.f, 0.f);
#pragma unroll
        for (int q = 0; q < 4; ++q) ((float4*)g_h0)[id * 4 + q] = z;
        if (blk == 512 && tid < 32) ((uint4*)g_bar)[tid] = make_uint4(0u, 0u, 0u, 0u);
    } else {                               // blk == 520: bc
        for (int c = tid; c < Hq; c += 256) {
            float acc = __ldg(b_pass + c);
            for (int u = 0; u < Hq; ++u)
                acc = fmaf(__ldg(b_in + u), __ldg(Wp + u * Hq + c), acc);
            g_bc[c] = acc;
        }
    }
}

// ---------------- k_pre2: WE (6 weight sets), MX, bias4 ----------------
__global__ void k_pre2(const float* __restrict__ Win, const float* __restrict__ Wp,
                       const float* __restrict__ Wt, const float* __restrict__ Wm,
                       const float* __restrict__ b_in, const float* __restrict__ b_tau,
                       const float* __restrict__ b_mem) {
    int blk = blockIdx.x, tid = threadIdx.x;
    if (blk < 1536) {
        // WE[v][jg][o][k]: h-part weight sets (k rows of Win, 0..511)
        int id = blk * 256 + tid;          // [0, 393216)
        int vo = id >> 16;                 // 0..5 = v*3+o
        int k = (id >> 7) & 511;
        int jq = (id & 127) << 2;
        int v = vo / 3, o = vo % 3;
        float o4[4];
        if (vo == 3) {                     // Q,o=0: Win copy (transpose to col-major)
            float4 w = __ldg((const float4*)(Win + k * Hq + jq));
            o4[0] = w.x; o4[1] = w.y; o4[2] = w.z; o4[3] = w.w;
        } else {
            const float* X = (vo == 0) ? Wp : (vo == 1) ? g_Pt : (vo == 2) ? g_Pm
                             : (vo == 4) ? Wt : Wm;
            float4 acc = make_float4(0.f, 0.f, 0.f, 0.f);
#pragma unroll 4
            for (int m = 0; m < Hq; ++m) {
                float a = __ldg(Win + k * Hq + m);
                float4 w = __ldg((const float4*)(X + m * Hq + jq));
                acc.x = fmaf(a, w.x, acc.x); acc.y = fmaf(a, w.y, acc.y);
                acc.z = fmaf(a, w.z, acc.z); acc.w = fmaf(a, w.w, acc.w);
            }
            o4[0] = acc.x; o4[1] = acc.y; o4[2] = acc.z; o4[3] = acc.w;
        }
#pragma unroll
        for (int u = 0; u < 4; ++u)
            g_WE[(((v * Hq + jq + u) * 3 + o) << 9) + k] = o4[u];
    } else if (blk < 1920) {
        // MX[v][k][jg*4+o]: x-part (rows 512..639 of Win)
        int id = (blk - 1536) * 256 + tid; // [0, 98304)
        int vo = id >> 14;                 // 0..5
        int k = (id >> 7) & 127;
        int jq = (id & 127) << 2;
        int v = vo / 3, o = vo % 3;
        float o4[4];
        if (vo == 3) {
            float4 w = __ldg((const float4*)(Win + (Hq + k) * Hq + jq));
            o4[0] = w.x; o4[1] = w.y; o4[2] = w.z; o4[3] = w.w;
        } else {
            const float* X = (vo == 0) ? Wp : (vo == 1) ? g_Pt : (vo == 2) ? g_Pm
                             : (vo == 4) ? Wt : Wm;
            float4 acc = make_float4(0.f, 0.f, 0.f, 0.f);
#pragma unroll 4
            for (int m = 0; m < Hq; ++m) {
                float a = __ldg(Win + (Hq + k) * Hq + m);
                float4 w = __ldg((const float4*)(X + m * Hq + jq));
                acc.x = fmaf(a, w.x, acc.x); acc.y = fmaf(a, w.y, acc.y);
                acc.z = fmaf(a, w.z, acc.z); acc.w = fmaf(a, w.w, acc.w);
            }
            o4[0] = acc.x; o4[1] = acc.y; o4[2] = acc.z; o4[3] = acc.w;
        }
#pragma unroll
        for (int u = 0; u < 4; ++u)
            g_MX[((v * Iq + k) << 11) + ((jq + u) << 2) + o] = o4[u];
    } else {
        // bias4[v][jg*4+o]
        for (int i = tid; i < 4096; i += 256) {
            int v = i >> 11, c = i & 2047, jg = c >> 2, o = c & 3;
            float val = 0.f;
            if (o == 0) {
                val = v ? __ldg(b_in + jg) : g_bc[jg];
            } else if (o < 3) {
                const float* G = (o == 1) ? Wt : Wm;
                float acc = (o == 1) ? __ldg(b_tau + jg) : __ldg(b_mem + jg);
                for (int m = 0; m < Hq; ++m) {
                    float bv = v ? __ldg(b_in + m) : g_bc[m];
                    acc = fmaf(bv, __ldg(G + m * Hq + jg), acc);
                }
                val = acc;
            }
            g_bias4[(v << 11) + c] = val;
        }
    }
}

// ---------------- k_xw: XW[b][t][2048] = x_t @ MX[v] + bias4[v] ----------------
__global__ void k_xw(const float* __restrict__ x, const int* __restrict__ lengths) {
    __shared__ float sh_x[64 * 129];
    int tid = threadIdx.x;
    int sb0 = blockIdx.x * 64;
    int cq0 = blockIdx.y * 4;
    for (int idx = tid; idx < 64 * 128; idx += 256) {
        int sl = idx >> 7, i = idx & 127;
        sh_x[sl * 129 + i] = x[(sb0 + sl) * Iq + i];
    }
    __syncthreads();
    int cql = tid >> 6, sl = tid & 63;
    int sb = sb0 + sl;
    int b = sb >> 8, t = sb & 255;
    int v = (t < __ldg(lengths + b)) ? 0 : 1;
    int cq = (cq0 + cql) << 2;
    float4 acc = __ldg((const float4*)(g_bias4 + (v << 11) + cq));
#pragma unroll 4
    for (int i = 0; i < Iq; ++i) {
        float a = sh_x[sl * 129 + i];
        float4 w = __ldg((const float4*)(g_MX + ((v * Iq + i) << 11) + cq));
        acc.x = fmaf(a, w.x, acc.x); acc.y = fmaf(a, w.y, acc.y);
        acc.z = fmaf(a, w.z, acc.z); acc.w = fmaf(a, w.w, acc.w);
    }
    *(float4*)(g_XW + ((size_t)sb << 11) + cq) = acc;
}

// ---------------- persistent RNN kernel ----------------

__device__ __forceinline__ void grid_barrier(unsigned* ctr, unsigned target) {
    __syncthreads();
    if (threadIdx.x == 0) {
        asm volatile("red.release.gpu.global.add.u32 [%0], %1;"
                     :: "l"(ctr), "r"(1u) : "memory");
        unsigned v;
        do {
            asm volatile("ld.relaxed.gpu.global.u32 %0, [%1];"
                         : "=r"(v) : "l"(ctr) : "memory");
        } while (v < target);
        asm volatile("ld.acquire.gpu.global.u32 %0, [%1];"
                     : "=r"(v) : "l"(ctr) : "memory");
    }
    __syncthreads();
}

// smem layout (floats)
#define SH_IN   0        // 16*516 = 8256
#define SH_RED  8256     // 1024
#define SH_MISC 9280     // 256
#define SH_BIAS 9536     // 32
#define SH_WO   9568     // 512
#define SH_W    10080    // 24772 (P block + pad + Q block)
#define SH_DB   34852    // 128*17 = 2176
#define SM_FLOATS 37028  // 148112 bytes

// fused 3-output GEMM partials: thread (r,j,kc), K=256 per thread
__device__ __forceinline__ void gemm3(const float* sh_in, const float* sh_w,
                                      float* sh_red, int r, int j, int kc, int voff) {
    const float* ap = sh_in + r * SHS + (kc << 8);
    const float* w0 = sh_w + voff + (j * 3) * WSTRIDE + (kc << 8);
    const float* w1 = w0 + WSTRIDE;
    const float* w2 = w0 + 2 * WSTRIDE;
    float a0 = 0.f, a1 = 0.f, a2 = 0.f;
#pragma unroll 8
    for (int k = 0; k < 256; k += 4) {
        float4 a = *(const float4*)(ap + k);
        float4 u = *(const float4*)(w0 + k);
        float4 v = *(const float4*)(w1 + k);
        float4 w = *(const float4*)(w2 + k);
        a0 = fmaf(a.x, u.x, a0); a0 = fmaf(a.y, u.y, a0);
        a0 = fmaf(a.z, u.z, a0); a0 = fmaf(a.w, u.w, a0);
        a1 = fmaf(a.x, v.x, a1); a1 = fmaf(a.y, v.y, a1);
        a1 = fmaf(a.z, v.z, a1); a1 = fmaf(a.w, v.w, a1);
        a2 = fmaf(a.x, w.x, a2); a2 = fmaf(a.y, w.y, a2);
        a2 = fmaf(a.z, w.z, a2); a2 = fmaf(a.w, w.w, a2);
    }
    int s = ((j * 16 + r) << 3) + (kc << 2);
    sh_red[s] = a0; sh_red[s + 1] = a1; sh_red[s + 2] = a2;
}

__global__ void __launch_bounds__(NTHR, 1) k_rnn(const int* __restrict__ lengths,
                                                 const float* __restrict__ W_out,
                                                 const float* __restrict__ b_out,
                                                 float* __restrict__ out) {
    extern __shared__ float sm[];
    float* sh_in   = sm + SH_IN;
    float* sh_red  = sm + SH_RED;
    float* sh_misc = sm + SH_MISC;
    float* sh_bias = sm + SH_BIAS;
    float* sh_wo   = sm + SH_WO;
    float* sh_w    = sm + SH_W;
    float* sh_db   = sm + SH_DB;
    int tid = threadIdx.x, cta = blockIdx.x;
    int grp = cta >> 6, cg = cta & 63;
    int b0 = grp * RB;
    int jg0 = cg * 8;
    unsigned* bar = g_bar + grp * 64;
    int r = tid & 15, j = (tid >> 4) & 7, kc = tid >> 7;

    // ---- preload: weight slices (both variants), biases, W_out col, zero dbuf ----
    for (int i = tid; i < 6144; i += NTHR) {
        int vec = i >> 7, kq = (i & 127) << 2;
        int v = vec / 24, rem = vec % 24;              // rem = jj*3+o
        int jj = rem / 3, o = rem % 3;
        *(float4*)(sh_w + v * QOFF + rem * WSTRIDE + kq) =
            *(const float4*)(g_WE + (((v * Hq + jg0 + jj) * 3 + o) << 9) + kq);
    }
    if (tid < 32) sh_bias[tid] = g_bias4[(jg0 << 2) + tid];   // P-variant decode bias
    for (int k = tid; k < Hq; k += NTHR) sh_wo[k] = __ldg(W_out + k * Cq + cg);
    for (int i = tid; i < 128 * BUFD; i += NTHR) sh_db[i] = 0.f;
    int lenr = __ldg(lengths + b0 + r);
    float bout_c = __ldg(b_out + cg);
    __syncthreads();

    unsigned nb = 0;
    int par = 0;

    // ---- encode: 256 steps, ONE barrier each ----
    for (int t = 0; t < Sq; ++t) {
        const float* src = g_h0 + par * (Bq * Hq) + b0 * Hq;
        for (int i = tid; i < 2048; i += NTHR) {
            int bb = i >> 7, h4 = (i & 127) << 2;
            *(float4*)(sh_in + bb * SHS + h4) = __ldcg((const float4*)(src + bb * Hq + h4));
        }
        float4 xw = make_float4(0.f, 0.f, 0.f, 0.f);
        if (tid < 128)
            xw = __ldcg((const float4*)(g_XW + (((size_t)(b0 + r) * Sq + t) << 11)
                                        + ((jg0 + j) << 2)));
        __syncthreads();
        gemm3(sh_in, sh_w, sh_red, r, j, kc, (t < lenr) ? 0 : QOFF);
        __syncthreads();
        if (tid < 128) {
            int s8 = tid << 3;
            float h  = sh_red[s8]     + sh_red[s8 + 4] + xw.x;
            float ti = sh_red[s8 + 1] + sh_red[s8 + 5] + xw.y;
            float mi = sh_red[s8 + 2] + sh_red[s8 + 6] + xw.z;
            float tau = __fdividef(16.f, 1.f + __expf(-ti));
            tau = fminf(fmaxf(tau, 1.f), 16.f);
            float mem = __fdividef(1.f, 1.f + __expf(-mi));
            float* dp = sh_db + tid * BUFD;
#pragma unroll
            for (int d = 0; d < 16; ++d) {
                float wq = __fdividef(mem, 1.f + fabsf(tau - (float)(d + 1)));
                dp[d] = fmaf(wq, h, dp[d + 1]);
            }
            dp[16] = 0.f;
            __stcg(g_h0 + (par ^ 1) * (Bq * Hq) + (b0 + r) * Hq + jg0 + j, dp[0]);
        }
        nb++; grid_barrier(bar, nb * GCTA);
        par ^= 1;
    }

    // ---- decode: 64 steps, ONE barrier each (P-variant, + out col cg) ----
    for (int t = 0; t < OUTL; ++t) {
        const float* src = g_h0 + par * (Bq * Hq) + b0 * Hq;
        for (int i = tid; i < 2048; i += NTHR) {
            int bb = i >> 7, h4 = (i & 127) << 2;
            *(float4*)(sh_in + bb * SHS + h4) = __ldcg((const float4*)(src + bb * Hq + h4));
        }
        __syncthreads();
        gemm3(sh_in, sh_w, sh_red, r, j, kc, 0);
        {   // out partials: thread (r2, kc2) over 32 K
            int r2 = tid & 15, kc2 = tid >> 4;
            const float* ap2 = sh_in + r2 * SHS + kc2 * 32;
            const float* wp2 = sh_wo + kc2 * 32;
            float acc = 0.f;
#pragma unroll 8
            for (int k = 0; k < 32; ++k) acc = fmaf(ap2[k], wp2[k], acc);
            sh_misc[tid] = acc;
        }
        __syncthreads();
        if (tid < 128) {
            int s8 = tid << 3, j4 = j << 2;
            float h  = sh_red[s8]     + sh_red[s8 + 4] + sh_bias[j4];
            float ti = sh_red[s8 + 1] + sh_red[s8 + 5] + sh_bias[j4 + 1];
            float mi = sh_red[s8 + 2] + sh_red[s8 + 6] + sh_bias[j4 + 2];
            float tau = __fdividef(16.f, 1.f + __expf(-ti));
            tau = fminf(fmaxf(tau, 1.f), 16.f);
            float mem = __fdividef(1.f, 1.f + __expf(-mi));
            float* dp = sh_db + tid * BUFD;
#pragma unroll
            for (int d = 0; d < 16; ++d) {
                float wq = __fdividef(mem, 1.f + fabsf(tau - (float)(d + 1)));
                dp[d] = fmaf(wq, h, dp[d + 1]);
            }
            dp[16] = 0.f;
            __stcg(g_h0 + (par ^ 1) * (Bq * Hq) + (b0 + r) * Hq + jg0 + j, dp[0]);
        } else if (tid < 144) {
            int r2 = tid - 128;
            float s = bout_c;
#pragma unroll
            for (int kc2 = 0; kc2 < 16; ++kc2) s += sh_misc[kc2 * 16 + r2];
            out[(b0 + r2) * (OUTL * Cq) + t * Cq + cg] = s;
        }
        nb++; grid_barrier(bar, nb * GCTA);
        par ^= 1;
    }
}

// ---------------- launch ----------------
extern "C" void kernel_launch(void* const* d_in, const int* in_sizes, int n_in,
                              void* d_out, int out_size) {
    const float* x       = (const float*)d_in[0];
    const int*   lengths = (const int*)d_in[1];
    int wi = 2;
    if (n_in >= 13 && in_sizes[2] == 1) wi = 3;
    const float* W_in   = (const float*)d_in[wi + 0];
    const float* b_in   = (const float*)d_in[wi + 1];
    const float* W_pass = (const float*)d_in[wi + 2];
    const float* b_pass = (const float*)d_in[wi + 3];
    const float* W_tau  = (const float*)d_in[wi + 4];
    const float* b_tau  = (const float*)d_in[wi + 5];
    const float* W_mem  = (const float*)d_in[wi + 6];
    const float* b_mem  = (const float*)d_in[wi + 7];
    const float* W_out  = (const float*)d_in[wi + 8];
    const float* b_out  = (const float*)d_in[wi + 9];
    float* out = (float*)d_out;

    static int smem_set = 0;
    const int smem_bytes = SM_FLOATS * (int)sizeof(float);   // 148112
    if (!smem_set) {
        cudaFuncSetAttribute(k_rnn, cudaFuncAttributeMaxDynamicSharedMemorySize, smem_bytes);
        smem_set = 1;
    }

    k_pre1<<<521, 256>>>(W_pass, W_tau, W_mem, b_in, b_pass);
    k_pre2<<<1921, 256>>>(W_in, W_pass, W_tau, W_mem, b_in, b_tau, b_mem);
    k_xw<<<dim3(128, 128), 256>>>(x, lengths);
    k_rnn<<<NCTA, NTHR, smem_bytes>>>(lengths, W_out, b_out, out);
}

// round 13
// speedup vs baseline: 1.0302x; 1.0302x over previous
#include <cuda_runtime.h>
#include <math.h>

// Problem dims
#define Bq   32
#define Sq   256
#define Iq   128
#define Hq   512
#define Cq   64
#define BUFD 17
#define OUTL 64

#define NCTA 128      // 2 groups x 64 CTAs
#define GCTA 64       // CTAs per group
#define RB   16       // batches per group
#define NTHR 256
#define WCOLS 24      // 8 h-cols * 3 outputs
#define WSTRIDE 516   // weight col stride (floats)
#define QOFF (WCOLS * WSTRIDE + 4)   // 12388: Q-variant block offset
#define CSTR 132      // chunk row stride (floats)

// ---------------- device globals ----------------
__device__ __align__(16) float g_Pt[Hq * Hq];        // W_pass @ W_tau
__device__ __align__(16) float g_Pm[Hq * Hq];        // W_pass @ W_mem
__device__ __align__(16) float g_bc[Hq];             // b_in @ W_pass + b_pass
__device__ __align__(16) float g_WE[2 * Hq * 3 * Hq];// [(v*512+jg)*3+o][k] col-major weight sets
__device__ __align__(16) float g_MX[2 * Iq * 2048];  // x-side matrices, [v][k][jg*4+o]
__device__ __align__(16) float g_bias4[2 * 2048];    // folded biases, [v][jg*4+o]
__device__ __align__(16) float g_XW[(size_t)Bq * Sq * 2048]; // per-(b,t) precomputed terms
__device__ __align__(16) float g_h0[2 * Bq * Hq];    // double-buffered h0 broadcast
__device__ unsigned g_bar[2 * 8 * 64];               // [group][8 sub-counters], 256B apart

// ---------------- k_pre1: Pt, Pm, bc, zero h0/bar ----------------
__global__ void k_pre1(const float* __restrict__ Wp, const float* __restrict__ Wt,
                       const float* __restrict__ Wm, const float* __restrict__ b_in,
                       const float* __restrict__ b_pass) {
    int blk = blockIdx.x, tid = threadIdx.x;
    if (blk < 512) {
        int id = blk * 256 + tid;          // [0, 131072)
        int mat = id >> 16;                // 0: Pt, 1: Pm
        int m = (id >> 7) & 511;
        int jq = (id & 127) << 2;
        const float* B = mat ? Wm : Wt;
        float4 acc = make_float4(0.f, 0.f, 0.f, 0.f);
#pragma unroll 4
        for (int u = 0; u < Hq; ++u) {
            float a = __ldg(Wp + m * Hq + u);
            float4 w = __ldg((const float4*)(B + u * Hq + jq));
            acc.x = fmaf(a, w.x, acc.x); acc.y = fmaf(a, w.y, acc.y);
            acc.z = fmaf(a, w.z, acc.z); acc.w = fmaf(a, w.w, acc.w);
        }
        *(float4*)((mat ? g_Pm : g_Pt) + m * Hq + jq) = acc;
    } else if (blk < 520) {
        int id = (blk - 512) * 256 + tid;  // [0, 2048): zero both h0 parities
        float4 z = make_float4(0.f, 0.f, 0.f, 0.f);
#pragma unroll
        for (int q = 0; q < 4; ++q) ((float4*)g_h0)[id * 4 + q] = z;
        if (blk == 512 && tid < 256)
            ((uint4*)g_bar)[tid] = make_uint4(0u, 0u, 0u, 0u);   // 1024 uints
    } else {                               // blk == 520: bc
        for (int c = tid; c < Hq; c += 256) {
            float acc = __ldg(b_pass + c);
            for (int u = 0; u < Hq; ++u)
                acc = fmaf(__ldg(b_in + u), __ldg(Wp + u * Hq + c), acc);
            g_bc[c] = acc;
        }
    }
}

// ---------------- k_pre2: WE (6 weight sets), MX, bias4 ----------------
__global__ void k_pre2(const float* __restrict__ Win, const float* __restrict__ Wp,
                       const float* __restrict__ Wt, const float* __restrict__ Wm,
                       const float* __restrict__ b_in, const float* __restrict__ b_tau,
                       const float* __restrict__ b_mem) {
    int blk = blockIdx.x, tid = threadIdx.x;
    if (blk < 1536) {
        int id = blk * 256 + tid;          // [0, 393216)
        int vo = id >> 16;                 // 0..5 = v*3+o
        int k = (id >> 7) & 511;
        int jq = (id & 127) << 2;
        int v = vo / 3, o = vo % 3;
        float o4[4];
        if (vo == 3) {
            float4 w = __ldg((const float4*)(Win + k * Hq + jq));
            o4[0] = w.x; o4[1] = w.y; o4[2] = w.z; o4[3] = w.w;
        } else {
            const float* X = (vo == 0) ? Wp : (vo == 1) ? g_Pt : (vo == 2) ? g_Pm
                             : (vo == 4) ? Wt : Wm;
            float4 acc = make_float4(0.f, 0.f, 0.f, 0.f);
#pragma unroll 4
            for (int m = 0; m < Hq; ++m) {
                float a = __ldg(Win + k * Hq + m);
                float4 w = __ldg((const float4*)(X + m * Hq + jq));
                acc.x = fmaf(a, w.x, acc.x); acc.y = fmaf(a, w.y, acc.y);
                acc.z = fmaf(a, w.z, acc.z); acc.w = fmaf(a, w.w, acc.w);
            }
            o4[0] = acc.x; o4[1] = acc.y; o4[2] = acc.z; o4[3] = acc.w;
        }
#pragma unroll
        for (int u = 0; u < 4; ++u)
            g_WE[(((v * Hq + jq + u) * 3 + o) << 9) + k] = o4[u];
    } else if (blk < 1920) {
        int id = (blk - 1536) * 256 + tid; // [0, 98304)
        int vo = id >> 14;
        int k = (id >> 7) & 127;
        int jq = (id & 127) << 2;
        int v = vo / 3, o = vo % 3;
        float o4[4];
        if (vo == 3) {
            float4 w = __ldg((const float4*)(Win + (Hq + k) * Hq + jq));
            o4[0] = w.x; o4[1] = w.y; o4[2] = w.z; o4[3] = w.w;
        } else {
            const float* X = (vo == 0) ? Wp : (vo == 1) ? g_Pt : (vo == 2) ? g_Pm
                             : (vo == 4) ? Wt : Wm;
            float4 acc = make_float4(0.f, 0.f, 0.f, 0.f);
#pragma unroll 4
            for (int m = 0; m < Hq; ++m) {
                float a = __ldg(Win + (Hq + k) * Hq + m);
                float4 w = __ldg((const float4*)(X + m * Hq + jq));
                acc.x = fmaf(a, w.x, acc.x); acc.y = fmaf(a, w.y, acc.y);
                acc.z = fmaf(a, w.z, acc.z); acc.w = fmaf(a, w.w, acc.w);
            }
            o4[0] = acc.x; o4[1] = acc.y; o4[2] = acc.z; o4[3] = acc.w;
        }
#pragma unroll
        for (int u = 0; u < 4; ++u)
            g_MX[((v * Iq + k) << 11) + ((jq + u) << 2) + o] = o4[u];
    } else {
        for (int i = tid; i < 4096; i += 256) {
            int v = i >> 11, c = i & 2047, jg = c >> 2, o = c & 3;
            float val = 0.f;
            if (o == 0) {
                val = v ? __ldg(b_in + jg) : g_bc[jg];
            } else if (o < 3) {
                const float* G = (o == 1) ? Wt : Wm;
                float acc = (o == 1) ? __ldg(b_tau + jg) : __ldg(b_mem + jg);
                for (int m = 0; m < Hq; ++m) {
                    float bv = v ? __ldg(b_in + m) : g_bc[m];
                    acc = fmaf(bv, __ldg(G + m * Hq + jg), acc);
                }
                val = acc;
            }
            g_bias4[(v << 11) + c] = val;
        }
    }
}

// ---------------- k_xw ----------------
__global__ void k_xw(const float* __restrict__ x, const int* __restrict__ lengths) {
    __shared__ float sh_x[64 * 129];
    int tid = threadIdx.x;
    int sb0 = blockIdx.x * 64;
    int cq0 = blockIdx.y * 4;
    for (int idx = tid; idx < 64 * 128; idx += 256) {
        int sl = idx >> 7, i = idx & 127;
        sh_x[sl * 129 + i] = x[(sb0 + sl) * Iq + i];
    }
    __syncthreads();
    int cql = tid >> 6, sl = tid & 63;
    int sb = sb0 + sl;
    int b = sb >> 8, t = sb & 255;
    int v = (t < __ldg(lengths + b)) ? 0 : 1;
    int cq = (cq0 + cql) << 2;
    float4 acc = __ldg((const float4*)(g_bias4 + (v << 11) + cq));
#pragma unroll 4
    for (int i = 0; i < Iq; ++i) {
        float a = sh_x[sl * 129 + i];
        float4 w = __ldg((const float4*)(g_MX + ((v * Iq + i) << 11) + cq));
        acc.x = fmaf(a, w.x, acc.x); acc.y = fmaf(a, w.y, acc.y);
        acc.z = fmaf(a, w.z, acc.z); acc.w = fmaf(a, w.w, acc.w);
    }
    *(float4*)(g_XW + ((size_t)sb << 11) + cq) = acc;
}

// ---------------- persistent RNN kernel ----------------

// 8 sub-counters, 256B apart; release-arrive, relaxed batched poll, acquire re-read
__device__ __forceinline__ void grid_barrier(unsigned* base, int sub, unsigned target) {
    __syncthreads();
    if (threadIdx.x == 0) {
        asm volatile("red.release.gpu.global.add.u32 [%0], %1;"
                     :: "l"(base + (sub << 6)), "r"(1u) : "memory");
        unsigned s;
        do {
            unsigned v0, v1, v2, v3, v4, v5, v6, v7;
            asm volatile("ld.relaxed.gpu.global.u32 %0, [%1];" : "=r"(v0) : "l"(base +   0) : "memory");
            asm volatile("ld.relaxed.gpu.global.u32 %0, [%1];" : "=r"(v1) : "l"(base +  64) : "memory");
            asm volatile("ld.relaxed.gpu.global.u32 %0, [%1];" : "=r"(v2) : "l"(base + 128) : "memory");
            asm volatile("ld.relaxed.gpu.global.u32 %0, [%1];" : "=r"(v3) : "l"(base + 192) : "memory");
            asm volatile("ld.relaxed.gpu.global.u32 %0, [%1];" : "=r"(v4) : "l"(base + 256) : "memory");
            asm volatile("ld.relaxed.gpu.global.u32 %0, [%1];" : "=r"(v5) : "l"(base + 320) : "memory");
            asm volatile("ld.relaxed.gpu.global.u32 %0, [%1];" : "=r"(v6) : "l"(base + 384) : "memory");
            asm volatile("ld.relaxed.gpu.global.u32 %0, [%1];" : "=r"(v7) : "l"(base + 448) : "memory");
            s = v0 + v1 + v2 + v3 + v4 + v5 + v6 + v7;
        } while (s < target);
        unsigned d;
        asm volatile("ld.acquire.gpu.global.u32 %0, [%1];" : "=r"(d) : "l"(base) : "memory");
    }
    __syncthreads();
}

// smem layout (floats)
#define SH_C    0        // 2 * 16*132 = 4224 (chunk double buffer)
#define SH_RED  4224     // 1024
#define SH_MISC 5248     // 256
#define SH_BIAS 5504     // 32
#define SH_WO   5536     // 512
#define SH_W    6048     // 24772 (P block + pad + Q block)
#define SH_DB   30820    // 2176
#define SM_FLOATS 32996  // 131984 bytes

// one K-chunk (64 k per thread) of the fused 3-output GEMM
__device__ __forceinline__ void gemm3_chunk(const float* cb, const float* w0p,
                                            int r, int kc,
                                            float& a0, float& a1, float& a2) {
    const float* ap = cb + r * CSTR + (kc << 6);
    const float* w0 = w0p + (kc << 6);
    const float* w1 = w0 + WSTRIDE;
    const float* w2 = w0 + 2 * WSTRIDE;
#pragma unroll
    for (int k = 0; k < 64; k += 4) {
        float4 a = *(const float4*)(ap + k);
        float4 u = *(const float4*)(w0 + k);
        float4 v = *(const float4*)(w1 + k);
        float4 w = *(const float4*)(w2 + k);
        a0 = fmaf(a.x, u.x, a0); a0 = fmaf(a.y, u.y, a0);
        a0 = fmaf(a.z, u.z, a0); a0 = fmaf(a.w, u.w, a0);
        a1 = fmaf(a.x, v.x, a1); a1 = fmaf(a.y, v.y, a1);
        a1 = fmaf(a.z, v.z, a1); a1 = fmaf(a.w, v.w, a1);
        a2 = fmaf(a.x, w.x, a2); a2 = fmaf(a.y, w.y, a2);
        a2 = fmaf(a.z, w.z, a2); a2 = fmaf(a.w, w.w, a2);
    }
}

__global__ void __launch_bounds__(NTHR, 1) k_rnn(const int* __restrict__ lengths,
                                                 const float* __restrict__ W_out,
                                                 const float* __restrict__ b_out,
                                                 float* __restrict__ out) {
    extern __shared__ float sm[];
    float* sh_c    = sm + SH_C;
    float* sh_red  = sm + SH_RED;
    float* sh_misc = sm + SH_MISC;
    float* sh_bias = sm + SH_BIAS;
    float* sh_wo   = sm + SH_WO;
    float* sh_w    = sm + SH_W;
    float* sh_db   = sm + SH_DB;
    int tid = threadIdx.x, cta = blockIdx.x;
    int grp = cta >> 6, cg = cta & 63;
    int b0 = grp * RB;
    int jg0 = cg * 8;
    unsigned* bar = g_bar + grp * 512;
    int sub = cg & 7;
    int r = tid & 15, j = (tid >> 4) & 7, kc = tid >> 7;
    // chunk-stage indices: i0/i1 cover 512 float4 (16 rows x 32 quads)
    int i0 = tid, i1 = tid + 256;
    int rw0 = i0 >> 5, qk0 = (i0 & 31) << 2;
    int rw1 = i1 >> 5, qk1 = (i1 & 31) << 2;

    // ---- preload: weight slices, biases, W_out col, zero dbuf ----
    for (int i = tid; i < 6144; i += NTHR) {
        int vec = i >> 7, kq = (i & 127) << 2;
        int v = vec / 24, rem = vec % 24;
        *(float4*)(sh_w + v * QOFF + rem * WSTRIDE + kq) =
            *(const float4*)(g_WE + (((v * Hq + jg0) * 3 + rem) << 9) + kq);
    }
    if (tid < 32) sh_bias[tid] = g_bias4[(jg0 << 2) + tid];
    for (int k = tid; k < Hq; k += NTHR) sh_wo[k] = __ldg(W_out + k * Cq + cg);
    for (int i = tid; i < 128 * BUFD; i += NTHR) sh_db[i] = 0.f;
    int lenr = __ldg(lengths + b0 + r);
    float bout_c = __ldg(b_out + cg);
    __syncthreads();

    unsigned nb = 0;
    int par = 0;

    // ---- encode: 256 steps ----
    for (int t = 0; t < Sq; ++t) {
        const float* src = g_h0 + par * (Bq * Hq) + b0 * Hq;
        float4 xw = make_float4(0.f, 0.f, 0.f, 0.f);
        if (tid < 128)
            xw = __ldcg((const float4*)(g_XW + (((size_t)(b0 + r) * Sq + t) << 11)
                                        + ((jg0 + j) << 2)));
        // chunk 0 stage
        float4 p0 = __ldcg((const float4*)(src + rw0 * Hq + qk0));
        float4 p1 = __ldcg((const float4*)(src + rw1 * Hq + qk1));
        *(float4*)(sh_c + rw0 * CSTR + qk0) = p0;
        *(float4*)(sh_c + rw1 * CSTR + qk1) = p1;
        __syncthreads();

        const float* wbase = sh_w + ((t < lenr) ? 0 : QOFF) + (j * 3) * WSTRIDE;
        float a0 = 0.f, a1 = 0.f, a2 = 0.f;
#pragma unroll
        for (int c = 0; c < 4; ++c) {
            float* cb = sh_c + (c & 1) * (16 * CSTR);
            if (c < 3) {
                p0 = __ldcg((const float4*)(src + rw0 * Hq + ((c + 1) << 7) + qk0));
                p1 = __ldcg((const float4*)(src + rw1 * Hq + ((c + 1) << 7) + qk1));
            }
            gemm3_chunk(cb, wbase + (c << 7), r, kc, a0, a1, a2);
            if (c < 3) {
                float* nbuf = sh_c + ((c + 1) & 1) * (16 * CSTR);
                *(float4*)(nbuf + rw0 * CSTR + qk0) = p0;
                *(float4*)(nbuf + rw1 * CSTR + qk1) = p1;
                __syncthreads();
            }
        }
        int s = ((j * 16 + r) << 3) + (kc << 2);
        sh_red[s] = a0; sh_red[s + 1] = a1; sh_red[s + 2] = a2;
        __syncthreads();
        if (tid < 128) {
            int s8 = tid << 3;
            float h  = sh_red[s8]     + sh_red[s8 + 4] + xw.x;
            float ti = sh_red[s8 + 1] + sh_red[s8 + 5] + xw.y;
            float mi = sh_red[s8 + 2] + sh_red[s8 + 6] + xw.z;
            float tau = __fdividef(16.f, 1.f + __expf(-ti));
            tau = fminf(fmaxf(tau, 1.f), 16.f);
            float mem = __fdividef(1.f, 1.f + __expf(-mi));
            float* dp = sh_db + tid * BUFD;
#pragma unroll
            for (int d = 0; d < 16; ++d) {
                float wq = __fdividef(mem, 1.f + fabsf(tau - (float)(d + 1)));
                dp[d] = fmaf(wq, h, dp[d + 1]);
            }
            dp[16] = 0.f;
            __stcg(g_h0 + (par ^ 1) * (Bq * Hq) + (b0 + r) * Hq + jg0 + j, dp[0]);
        }
        nb++; grid_barrier(bar, sub, nb * GCTA);
        par ^= 1;
    }

    // ---- decode: 64 steps (P-variant; out col cg folded into chunk loop) ----
    int r2 = tid & 15, s2 = tid >> 4;
    for (int t = 0; t < OUTL; ++t) {
        const float* src = g_h0 + par * (Bq * Hq) + b0 * Hq;
        float4 p0 = __ldcg((const float4*)(src + rw0 * Hq + qk0));
        float4 p1 = __ldcg((const float4*)(src + rw1 * Hq + qk1));
        *(float4*)(sh_c + rw0 * CSTR + qk0) = p0;
        *(float4*)(sh_c + rw1 * CSTR + qk1) = p1;
        __syncthreads();

        const float* wbase = sh_w + (j * 3) * WSTRIDE;
        float a0 = 0.f, a1 = 0.f, a2 = 0.f, aco = 0.f;
#pragma unroll
        for (int c = 0; c < 4; ++c) {
            float* cb = sh_c + (c & 1) * (16 * CSTR);
            if (c < 3) {
                p0 = __ldcg((const float4*)(src + rw0 * Hq + ((c + 1) << 7) + qk0));
                p1 = __ldcg((const float4*)(src + rw1 * Hq + ((c + 1) << 7) + qk1));
            }
            gemm3_chunk(cb, wbase + (c << 7), r, kc, a0, a1, a2);
            {   // out-col partial: 8 k per thread per chunk
                const float* ap2 = cb + r2 * CSTR + s2 * 8;
                const float* wp2 = sh_wo + (c << 7) + s2 * 8;
#pragma unroll
                for (int k = 0; k < 8; ++k) aco = fmaf(ap2[k], wp2[k], aco);
            }
            if (c < 3) {
                float* nbuf = sh_c + ((c + 1) & 1) * (16 * CSTR);
                *(float4*)(nbuf + rw0 * CSTR + qk0) = p0;
                *(float4*)(nbuf + rw1 * CSTR + qk1) = p1;
                __syncthreads();
            }
        }
        int s = ((j * 16 + r) << 3) + (kc << 2);
        sh_red[s] = a0; sh_red[s + 1] = a1; sh_red[s + 2] = a2;
        sh_misc[tid] = aco;
        __syncthreads();
        if (tid < 128) {
            int s8 = tid << 3, j4 = j << 2;
            float h  = sh_red[s8]     + sh_red[s8 + 4] + sh_bias[j4];
            float ti = sh_red[s8 + 1] + sh_red[s8 + 5] + sh_bias[j4 + 1];
            float mi = sh_red[s8 + 2] + sh_red[s8 + 6] + sh_bias[j4 + 2];
            float tau = __fdividef(16.f, 1.f + __expf(-ti));
            tau = fminf(fmaxf(tau, 1.f), 16.f);
            float mem = __fdividef(1.f, 1.f + __expf(-mi));
            float* dp = sh_db + tid * BUFD;
#pragma unroll
            for (int d = 0; d < 16; ++d) {
                float wq = __fdividef(mem, 1.f + fabsf(tau - (float)(d + 1)));
                dp[d] = fmaf(wq, h, dp[d + 1]);
            }
            dp[16] = 0.f;
            __stcg(g_h0 + (par ^ 1) * (Bq * Hq) + (b0 + r) * Hq + jg0 + j, dp[0]);
        } else if (tid < 144) {
            int rr = tid - 128;
            float sv = bout_c;
#pragma unroll
            for (int ss = 0; ss < 16; ++ss) sv += sh_misc[ss * 16 + rr];
            out[(b0 + rr) * (OUTL * Cq) + t * Cq + cg] = sv;
        }
        nb++; grid_barrier(bar, sub, nb * GCTA);
        par ^= 1;
    }
}

// ---------------- launch ----------------
extern "C" void kernel_launch(void* const* d_in, const int* in_sizes, int n_in,
                              void* d_out, int out_size) {
    const float* x       = (const float*)d_in[0];
    const int*   lengths = (const int*)d_in[1];
    int wi = 2;
    if (n_in >= 13 && in_sizes[2] == 1) wi = 3;
    const float* W_in   = (const float*)d_in[wi + 0];
    const float* b_in   = (const float*)d_in[wi + 1];
    const float* W_pass = (const float*)d_in[wi + 2];
    const float* b_pass = (const float*)d_in[wi + 3];
    const float* W_tau  = (const float*)d_in[wi + 4];
    const float* b_tau  = (const float*)d_in[wi + 5];
    const float* W_mem  = (const float*)d_in[wi + 6];
    const float* b_mem  = (const float*)d_in[wi + 7];
    const float* W_out  = (const float*)d_in[wi + 8];
    const float* b_out  = (const float*)d_in[wi + 9];
    float* out = (float*)d_out;

    static int smem_set = 0;
    const int smem_bytes = SM_FLOATS * (int)sizeof(float);   // 131984
    if (!smem_set) {
        cudaFuncSetAttribute(k_rnn, cudaFuncAttributeMaxDynamicSharedMemorySize, smem_bytes);
        smem_set = 1;
    }

    k_pre1<<<521, 256>>>(W_pass, W_tau, W_mem, b_in, b_pass);
    k_pre2<<<1921, 256>>>(W_in, W_pass, W_tau, W_mem, b_in, b_tau, b_mem);
    k_xw<<<dim3(128, 128), 256>>>(x, lengths);
    k_rnn<<<NCTA, NTHR, smem_bytes>>>(lengths, W_out, b_out, out);
}